// round 1
// baseline (speedup 1.0000x reference)
#include <cuda_runtime.h>
#include <cuda_fp16.h>
#include <mma.h>

using namespace nvcuda;

static constexpr int M_TOT = 8192;   // B * S = 4 * 2048
static constexpr int N_TOT = 4096;   // D_OUT
static constexpr int K_TOT = 4096;   // D_IN

static constexpr int BM = 128;
static constexpr int BN = 64;
static constexpr int BK = 64;
static constexpr int KPAD = BK + 8;   // 72 halves per smem row (pad vs bank conflicts)
static constexpr int CPAD = BN + 4;   // 68 floats per smem C row

// Scratch (allocation-free rule: __device__ globals)
__device__ __align__(16) __half g_xh[(size_t)M_TOT * K_TOT];   // 64 MiB
__device__ __align__(16) __half g_wh[(size_t)N_TOT * K_TOT];   // 32 MiB

// ---------------------------------------------------------------------------
// Conversion kernels: fp32 -> fp16 (x), int32 -> fp16 (w, exact for [-128,127])
// ---------------------------------------------------------------------------
__global__ void convert_x_kernel(const float* __restrict__ x, int n4) {
    int i = blockIdx.x * blockDim.x + threadIdx.x;
    if (i >= n4) return;
    float4 v = reinterpret_cast<const float4*>(x)[i];
    __half2* dst = reinterpret_cast<__half2*>(g_xh);
    dst[2 * i]     = __floats2half2_rn(v.x, v.y);
    dst[2 * i + 1] = __floats2half2_rn(v.z, v.w);
}

__global__ void convert_w_kernel(const int* __restrict__ w, int n4) {
    int i = blockIdx.x * blockDim.x + threadIdx.x;
    if (i >= n4) return;
    int4 v = reinterpret_cast<const int4*>(w)[i];
    __half2* dst = reinterpret_cast<__half2*>(g_wh);
    dst[2 * i]     = __halves2half2(__int2half_rn(v.x), __int2half_rn(v.y));
    dst[2 * i + 1] = __halves2half2(__int2half_rn(v.z), __int2half_rn(v.w));
}

// ---------------------------------------------------------------------------
// GEMM: out[m][n] = scale[n] * sum_k xh[m][k] * wh[n][k] + bias[n]
// Block tile 128x64, BK=64. 8 warps in 4x2 layout, each warp 32x32 (2x2 wmma).
// A row_major [M,K]; B fragment col_major over W^T (W is [N,K] row-major).
// ---------------------------------------------------------------------------
__global__ __launch_bounds__(256, 2)
void qgemm_kernel(const float* __restrict__ scale,
                  const float* __restrict__ bias,
                  float* __restrict__ out) {
    // smem: phase 1 holds A(128x72 half)+B(64x72 half)=27648 B;
    // phase 2 reuses it as C tile 128x68 f32 = 34816 B.
    __shared__ __align__(16) unsigned char smem_raw[(size_t)BM * CPAD * sizeof(float)];
    __half (*As)[KPAD] = reinterpret_cast<__half(*)[KPAD]>(smem_raw);
    __half (*Bs)[KPAD] = reinterpret_cast<__half(*)[KPAD]>(
        smem_raw + (size_t)BM * KPAD * sizeof(__half));
    float (*Cs)[CPAD] = reinterpret_cast<float(*)[CPAD]>(smem_raw);

    const int bm = blockIdx.y * BM;
    const int bn = blockIdx.x * BN;
    const int tid = threadIdx.x;
    const int warp = tid >> 5;
    const int wm = (warp >> 1) * 32;   // warp row offset within tile (0..96)
    const int wn = (warp & 1) * 32;    // warp col offset within tile (0 or 32)

    wmma::fragment<wmma::accumulator, 16, 16, 16, float> c[2][2];
#pragma unroll
    for (int i = 0; i < 2; i++)
#pragma unroll
        for (int j = 0; j < 2; j++)
            wmma::fill_fragment(c[i][j], 0.0f);

    const __half* A = g_xh;
    const __half* B = g_wh;

    for (int k0 = 0; k0 < K_TOT; k0 += BK) {
        // Load A tile: 128 rows x 64 halves = 1024 int4 transfers
#pragma unroll
        for (int t = tid; t < BM * (BK / 8); t += 256) {
            int r = t / (BK / 8);
            int c8 = t % (BK / 8);
            *reinterpret_cast<int4*>(&As[r][c8 * 8]) =
                *reinterpret_cast<const int4*>(&A[(size_t)(bm + r) * K_TOT + k0 + c8 * 8]);
        }
        // Load B tile: 64 rows x 64 halves = 512 int4 transfers
#pragma unroll
        for (int t = tid; t < BN * (BK / 8); t += 256) {
            int r = t / (BK / 8);
            int c8 = t % (BK / 8);
            *reinterpret_cast<int4*>(&Bs[r][c8 * 8]) =
                *reinterpret_cast<const int4*>(&B[(size_t)(bn + r) * K_TOT + k0 + c8 * 8]);
        }
        __syncthreads();

#pragma unroll
        for (int kk = 0; kk < BK; kk += 16) {
            wmma::fragment<wmma::matrix_a, 16, 16, 16, __half, wmma::row_major> a[2];
            wmma::fragment<wmma::matrix_b, 16, 16, 16, __half, wmma::col_major> b[2];
#pragma unroll
            for (int i = 0; i < 2; i++)
                wmma::load_matrix_sync(a[i], &As[wm + 16 * i][kk], KPAD);
#pragma unroll
            for (int j = 0; j < 2; j++)
                wmma::load_matrix_sync(b[j], &Bs[wn + 16 * j][kk], KPAD);
#pragma unroll
            for (int i = 0; i < 2; i++)
#pragma unroll
                for (int j = 0; j < 2; j++)
                    wmma::mma_sync(c[i][j], a[i], b[j], c[i][j]);
        }
        __syncthreads();
    }

    // Epilogue: stage accumulators through smem, apply scale/bias, vectorized store
#pragma unroll
    for (int i = 0; i < 2; i++)
#pragma unroll
        for (int j = 0; j < 2; j++)
            wmma::store_matrix_sync(&Cs[wm + 16 * i][wn + 16 * j], c[i][j],
                                    CPAD, wmma::mem_row_major);
    __syncthreads();

#pragma unroll
    for (int t = tid; t < BM * (BN / 4); t += 256) {
        int r = t / (BN / 4);
        int c4 = (t % (BN / 4)) * 4;
        float4 v = *reinterpret_cast<const float4*>(&Cs[r][c4]);
        float4 s = *reinterpret_cast<const float4*>(&scale[bn + c4]);
        float4 bb = *reinterpret_cast<const float4*>(&bias[bn + c4]);
        float4 o;
        o.x = fmaf(v.x, s.x, bb.x);
        o.y = fmaf(v.y, s.y, bb.y);
        o.z = fmaf(v.z, s.z, bb.z);
        o.w = fmaf(v.w, s.w, bb.w);
        *reinterpret_cast<float4*>(&out[(size_t)(bm + r) * N_TOT + bn + c4]) = o;
    }
}

// ---------------------------------------------------------------------------
// Launch
// ---------------------------------------------------------------------------
extern "C" void kernel_launch(void* const* d_in, const int* in_sizes, int n_in,
                              void* d_out, int out_size) {
    const float* x     = (const float*)d_in[0];   // [4,2048,4096] fp32
    const int*   w_q   = (const int*)d_in[1];     // [4096,4096] int32
    const float* scale = (const float*)d_in[2];   // [4096]
    const float* bias  = (const float*)d_in[3];   // [4096]
    float* out = (float*)d_out;                   // [4,2048,4096] fp32

    {
        int n4 = (M_TOT * K_TOT) / 4;  // 8388608
        convert_x_kernel<<<(n4 + 255) / 256, 256>>>(x, n4);
    }
    {
        int n4 = (N_TOT * K_TOT) / 4;  // 4194304
        convert_w_kernel<<<(n4 + 255) / 256, 256>>>(w_q, n4);
    }
    {
        dim3 grid(N_TOT / BN, M_TOT / BM);  // (64, 64)
        qgemm_kernel<<<grid, 256>>>(scale, bias, out);
    }
}

// round 3
// speedup vs baseline: 1.5623x; 1.5623x over previous
#include <cuda_runtime.h>
#include <cuda_fp16.h>
#include <cstdint>

static constexpr int M_TOT = 8192;   // B * S
static constexpr int N_TOT = 4096;   // D_OUT
static constexpr int K_TOT = 4096;   // D_IN

static constexpr int BM = 128;
static constexpr int BN = 256;
static constexpr int BK = 64;
static constexpr int STAGES = 3;
static constexpr int KITERS = K_TOT / BK;          // 64
static constexpr int ROW_BYTES = BK * 2;           // 128 B rows (SW128 atom)
static constexpr int A_BYTES = BM * ROW_BYTES;     // 16384
static constexpr int B_BYTES = BN * ROW_BYTES;     // 32768
static constexpr int STAGE_BYTES = A_BYTES + B_BYTES;  // 49152

static constexpr int OFF_SCALE = 0;                // 256 f32
static constexpr int OFF_BIAS  = 1024;             // 256 f32
static constexpr int OFF_TILES = 2048;             // keep 1024-aligned stage bases? 2048 ok (mult of 1024)
static constexpr int SMEM_TOTAL = OFF_TILES + STAGES * STAGE_BYTES;  // 149504

// Scratch fp16 operands (allocation-free rule: __device__ globals)
__device__ __align__(16) __half g_xh[(size_t)M_TOT * K_TOT];   // 64 MiB
__device__ __align__(16) __half g_wh[(size_t)N_TOT * K_TOT];   // 32 MiB

// ---------------------------------------------------------------------------
// helpers
// ---------------------------------------------------------------------------
__device__ __forceinline__ uint32_t smem_u32(const void* p) {
    uint32_t a;
    asm("{ .reg .u64 t; cvta.to.shared.u64 t, %1; cvt.u32.u64 %0, t; }" : "=r"(a) : "l"(p));
    return a;
}
__device__ __forceinline__ uint32_t swz(uint32_t byte_off) {
    return byte_off ^ ((byte_off >> 3) & 0x70);
}
__device__ __forceinline__ void cp_async16(uint32_t saddr, const void* gptr) {
    asm volatile("cp.async.cg.shared.global [%0], [%1], 16;" :: "r"(saddr), "l"(gptr));
}
#define CP_COMMIT() asm volatile("cp.async.commit_group;" ::: "memory")
#define CP_WAIT1()  asm volatile("cp.async.wait_group 1;" ::: "memory")

__device__ __forceinline__ void ldsm_x4(uint32_t& r0, uint32_t& r1,
                                        uint32_t& r2, uint32_t& r3, uint32_t addr) {
    asm volatile("ldmatrix.sync.aligned.m8n8.x4.shared.b16 {%0,%1,%2,%3}, [%4];"
                 : "=r"(r0), "=r"(r1), "=r"(r2), "=r"(r3) : "r"(addr));
}
__device__ __forceinline__ void mma16816(float& c0, float& c1, float& c2, float& c3,
                                         uint32_t a0, uint32_t a1, uint32_t a2, uint32_t a3,
                                         uint32_t b0, uint32_t b1) {
    asm volatile(
        "mma.sync.aligned.m16n8k16.row.col.f32.f16.f16.f32 "
        "{%0,%1,%2,%3}, {%4,%5,%6,%7}, {%8,%9}, {%0,%1,%2,%3};"
        : "+f"(c0), "+f"(c1), "+f"(c2), "+f"(c3)
        : "r"(a0), "r"(a1), "r"(a2), "r"(a3), "r"(b0), "r"(b1));
}

// ---------------------------------------------------------------------------
// conversion kernels (DRAM-streaming bound, ~33 + ~17 us)
// ---------------------------------------------------------------------------
__global__ void convert_x_kernel(const float* __restrict__ x, int n4) {
    int i = blockIdx.x * blockDim.x + threadIdx.x;
    if (i >= n4) return;
    float4 v = reinterpret_cast<const float4*>(x)[i];
    __half2* dst = reinterpret_cast<__half2*>(g_xh);
    dst[2 * i]     = __floats2half2_rn(v.x, v.y);
    dst[2 * i + 1] = __floats2half2_rn(v.z, v.w);
}
__global__ void convert_w_kernel(const int* __restrict__ w, int n4) {
    int i = blockIdx.x * blockDim.x + threadIdx.x;
    if (i >= n4) return;
    int4 v = reinterpret_cast<const int4*>(w)[i];
    __half2* dst = reinterpret_cast<__half2*>(g_wh);
    dst[2 * i]     = __halves2half2(__int2half_rn(v.x), __int2half_rn(v.y));
    dst[2 * i + 1] = __halves2half2(__int2half_rn(v.z), __int2half_rn(v.w));
}

// ---------------------------------------------------------------------------
// stage loader: 3072 x 16B cp.async (A: 1024, B: 2048 chunks), SW128 swizzle
// ---------------------------------------------------------------------------
__device__ __forceinline__ void load_stage(int tid, uint32_t stage_base,
                                           int bm, int bn, int k0) {
#pragma unroll
    for (int i = 0; i < 12; i++) {
        int idx = tid + i * 256;
        if (idx < 1024) {
            int row = idx >> 3, c16 = idx & 7;
            uint32_t sw = swz((uint32_t)(row * ROW_BYTES + c16 * 16));
            cp_async16(stage_base + sw,
                       g_xh + (size_t)(bm + row) * K_TOT + k0 + c16 * 8);
        } else {
            int j = idx - 1024;
            int row = j >> 3, c16 = j & 7;
            uint32_t sw = swz((uint32_t)(row * ROW_BYTES + c16 * 16));
            cp_async16(stage_base + A_BYTES + sw,
                       g_wh + (size_t)(bn + row) * K_TOT + k0 + c16 * 8);
        }
    }
}

// ---------------------------------------------------------------------------
// GEMM: 128x256 block tile, BK=64, 3-stage cp.async, 8 warps x (64x64) tiles
// ---------------------------------------------------------------------------
__global__ __launch_bounds__(256, 1)
void qgemm_mma_kernel(const float* __restrict__ scale,
                      const float* __restrict__ bias,
                      float* __restrict__ out) {
    extern __shared__ __align__(1024) char smem[];
    const uint32_t sbase = smem_u32(smem);
    const int tid = threadIdx.x;
    const int wid = tid >> 5;
    const int l = tid & 31;

    const int bm = blockIdx.y * BM;
    const int bn = blockIdx.x * BN;
    const int wm = (wid & 1) * 64;     // warp M offset within tile
    const int wn = (wid >> 1) * 64;    // warp N offset within tile

    // scale/bias for this N tile into smem
    reinterpret_cast<float*>(smem + OFF_SCALE)[tid] = scale[bn + tid];
    reinterpret_cast<float*>(smem + OFF_BIAS)[tid]  = bias[bn + tid];

    float acc[4][8][4];
#pragma unroll
    for (int mi = 0; mi < 4; mi++)
#pragma unroll
        for (int ni = 0; ni < 8; ni++)
#pragma unroll
            for (int r = 0; r < 4; r++) acc[mi][ni][r] = 0.0f;

    // prologue: stages 0,1
    load_stage(tid, sbase + OFF_TILES + 0 * STAGE_BYTES, bm, bn, 0);
    CP_COMMIT();
    load_stage(tid, sbase + OFF_TILES + 1 * STAGE_BYTES, bm, bn, BK);
    CP_COMMIT();

    // per-lane ldmatrix address components (swizzle XOR is constant per lane:
    // row&7 == l&7 for both A and B since wm/wn/16*mi/8*nt are multiples of 8)
    const uint32_t lxor = (uint32_t)((l & 7) << 4);
    const uint32_t a_row_off = (uint32_t)((wm + (l & 15)) * ROW_BYTES);
    const uint32_t a_khalf   = (uint32_t)((l >> 4) * 16);
    const uint32_t b_row_off = (uint32_t)((wn + (l & 7)) * ROW_BYTES);
    const int quad = l >> 3;
    const uint32_t b_nt_off  = (uint32_t)(((quad >> 1) * 8) * ROW_BYTES);
    const uint32_t b_khalf   = (uint32_t)((quad & 1) * 16);

    for (int it = 0; it < KITERS; it++) {
        CP_WAIT1();
        __syncthreads();

        // issue next stage's loads first (overlap with compute)
        const int nxt = it + 2;
        if (nxt < KITERS)
            load_stage(tid, sbase + OFF_TILES + (nxt % 3) * STAGE_BYTES, bm, bn, nxt * BK);
        CP_COMMIT();

        const uint32_t stA = sbase + OFF_TILES + (it % 3) * STAGE_BYTES;
        const uint32_t stB = stA + A_BYTES;

#pragma unroll
        for (int kk = 0; kk < 4; kk++) {            // k16 steps within BK=64
            uint32_t a[4][4], b[8][2];
#pragma unroll
            for (int mi = 0; mi < 4; mi++) {
                uint32_t addr = stA + a_row_off + (uint32_t)(mi * 16 * ROW_BYTES)
                              + (((uint32_t)(kk * 32) + a_khalf) ^ lxor);
                ldsm_x4(a[mi][0], a[mi][1], a[mi][2], a[mi][3], addr);
            }
#pragma unroll
            for (int nj = 0; nj < 4; nj++) {        // pairs of n8 tiles
                uint32_t addr = stB + b_row_off + (uint32_t)(nj * 16 * ROW_BYTES) + b_nt_off
                              + (((uint32_t)(kk * 32) + b_khalf) ^ lxor);
                ldsm_x4(b[nj * 2][0], b[nj * 2][1], b[nj * 2 + 1][0], b[nj * 2 + 1][1], addr);
            }
#pragma unroll
            for (int mi = 0; mi < 4; mi++)
#pragma unroll
                for (int ni = 0; ni < 8; ni++)
                    mma16816(acc[mi][ni][0], acc[mi][ni][1], acc[mi][ni][2], acc[mi][ni][3],
                             a[mi][0], a[mi][1], a[mi][2], a[mi][3],
                             b[ni][0], b[ni][1]);
        }
    }

    // epilogue: scale/bias from smem, direct 8B stores
    const float* s_scale = reinterpret_cast<const float*>(smem + OFF_SCALE);
    const float* s_bias  = reinterpret_cast<const float*>(smem + OFF_BIAS);
    const int row0 = bm + wm + (l >> 2);
    const int col0 = wn + (l & 3) * 2;

#pragma unroll
    for (int mi = 0; mi < 4; mi++) {
#pragma unroll
        for (int ni = 0; ni < 8; ni++) {
            const int n = col0 + ni * 8;
            const float s0 = s_scale[n], s1 = s_scale[n + 1];
            const float b0 = s_bias[n],  b1 = s_bias[n + 1];
            float* p0 = out + (size_t)(row0 + mi * 16) * N_TOT + bn + n;
            float* p1 = p0 + 8 * N_TOT;
            float2 v0 = make_float2(fmaf(acc[mi][ni][0], s0, b0),
                                    fmaf(acc[mi][ni][1], s1, b1));
            float2 v1 = make_float2(fmaf(acc[mi][ni][2], s0, b0),
                                    fmaf(acc[mi][ni][3], s1, b1));
            *reinterpret_cast<float2*>(p0) = v0;
            *reinterpret_cast<float2*>(p1) = v1;
        }
    }
}

// ---------------------------------------------------------------------------
// launch
// ---------------------------------------------------------------------------
extern "C" void kernel_launch(void* const* d_in, const int* in_sizes, int n_in,
                              void* d_out, int out_size) {
    const float* x     = (const float*)d_in[0];
    const int*   w_q   = (const int*)d_in[1];
    const float* scale = (const float*)d_in[2];
    const float* bias  = (const float*)d_in[3];
    float* out = (float*)d_out;

    {
        int n4 = (M_TOT * K_TOT) / 4;
        convert_x_kernel<<<(n4 + 255) / 256, 256>>>(x, n4);
    }
    {
        int n4 = (N_TOT * K_TOT) / 4;
        convert_w_kernel<<<(n4 + 255) / 256, 256>>>(w_q, n4);
    }
    {
        static bool attr_set = false;
        if (!attr_set) {
            cudaFuncSetAttribute(qgemm_mma_kernel,
                                 cudaFuncAttributeMaxDynamicSharedMemorySize, SMEM_TOTAL);
            attr_set = true;
        }
        dim3 grid(N_TOT / BN, M_TOT / BM);  // (16, 64): x-fast shares A tiles in L2
        qgemm_mma_kernel<<<grid, 256, SMEM_TOTAL>>>(scale, bias, out);
    }
}

// round 5
// speedup vs baseline: 1.5985x; 1.0232x over previous
#include <cuda_runtime.h>
#include <cuda_fp16.h>
#include <cstdint>

static constexpr int M_TOT = 8192;   // B * S
static constexpr int N_TOT = 4096;   // D_OUT
static constexpr int K_TOT = 4096;   // D_IN

static constexpr int BM = 128;
static constexpr int BN = 256;
static constexpr int BK = 64;
static constexpr int STAGES = 3;
static constexpr int KITERS = K_TOT / BK;          // 64
static constexpr int ROW_BYTES = BK * 2;           // 128 B rows (SW128 atom)
static constexpr int A_BYTES = BM * ROW_BYTES;     // 16384
static constexpr int B_BYTES = BN * ROW_BYTES;     // 32768
static constexpr int STAGE_BYTES = A_BYTES + B_BYTES;  // 49152

static constexpr int NTHREADS = 512;               // 16 warps, 4 per SMSP

static constexpr int OFF_SCALE = 0;                // 256 f32
static constexpr int OFF_BIAS  = 1024;             // 256 f32
static constexpr int OFF_TILES = 2048;
static constexpr int SMEM_TOTAL = OFF_TILES + STAGES * STAGE_BYTES;  // 149504

// Scratch fp16 operands (allocation-free rule: __device__ globals)
__device__ __align__(16) __half g_xh[(size_t)M_TOT * K_TOT];   // 64 MiB
__device__ __align__(16) __half g_wh[(size_t)N_TOT * K_TOT];   // 32 MiB

// ---------------------------------------------------------------------------
// helpers
// ---------------------------------------------------------------------------
__device__ __forceinline__ uint32_t smem_u32(const void* p) {
    uint32_t a;
    asm("{ .reg .u64 t; cvta.to.shared.u64 t, %1; cvt.u32.u64 %0, t; }" : "=r"(a) : "l"(p));
    return a;
}
__device__ __forceinline__ uint32_t swz(uint32_t byte_off) {
    return byte_off ^ ((byte_off >> 3) & 0x70);
}
__device__ __forceinline__ void cp_async16(uint32_t saddr, const void* gptr) {
    asm volatile("cp.async.cg.shared.global [%0], [%1], 16;" :: "r"(saddr), "l"(gptr));
}
#define CP_COMMIT() asm volatile("cp.async.commit_group;" ::: "memory")
#define CP_WAIT1()  asm volatile("cp.async.wait_group 1;" ::: "memory")

__device__ __forceinline__ void ldsm_x4(uint32_t& r0, uint32_t& r1,
                                        uint32_t& r2, uint32_t& r3, uint32_t addr) {
    asm volatile("ldmatrix.sync.aligned.m8n8.x4.shared.b16 {%0,%1,%2,%3}, [%4];"
                 : "=r"(r0), "=r"(r1), "=r"(r2), "=r"(r3) : "r"(addr));
}
__device__ __forceinline__ void mma16816(float& c0, float& c1, float& c2, float& c3,
                                         uint32_t a0, uint32_t a1, uint32_t a2, uint32_t a3,
                                         uint32_t b0, uint32_t b1) {
    asm volatile(
        "mma.sync.aligned.m16n8k16.row.col.f32.f16.f16.f32 "
        "{%0,%1,%2,%3}, {%4,%5,%6,%7}, {%8,%9}, {%0,%1,%2,%3};"
        : "+f"(c0), "+f"(c1), "+f"(c2), "+f"(c3)
        : "r"(a0), "r"(a1), "r"(a2), "r"(a3), "r"(b0), "r"(b1));
}

// ---------------------------------------------------------------------------
// conversion kernels (DRAM-streaming bound)
// ---------------------------------------------------------------------------
__global__ void convert_x_kernel(const float* __restrict__ x, int n4) {
    int i = blockIdx.x * blockDim.x + threadIdx.x;
    if (i >= n4) return;
    float4 v = reinterpret_cast<const float4*>(x)[i];
    __half2* dst = reinterpret_cast<__half2*>(g_xh);
    dst[2 * i]     = __floats2half2_rn(v.x, v.y);
    dst[2 * i + 1] = __floats2half2_rn(v.z, v.w);
}
__global__ void convert_w_kernel(const int* __restrict__ w, int n4) {
    int i = blockIdx.x * blockDim.x + threadIdx.x;
    if (i >= n4) return;
    int4 v = reinterpret_cast<const int4*>(w)[i];
    __half2* dst = reinterpret_cast<__half2*>(g_wh);
    dst[2 * i]     = __halves2half2(__int2half_rn(v.x), __int2half_rn(v.y));
    dst[2 * i + 1] = __halves2half2(__int2half_rn(v.z), __int2half_rn(v.w));
}

// ---------------------------------------------------------------------------
// stage loader: 3072 x 16B cp.async (A: 1024, B: 2048 chunks), SW128 swizzle
// ---------------------------------------------------------------------------
__device__ __forceinline__ void load_stage(int tid, uint32_t stage_base,
                                           int bm, int bn, int k0) {
#pragma unroll
    for (int i = 0; i < 6; i++) {
        int idx = tid + i * NTHREADS;
        if (idx < 1024) {
            int row = idx >> 3, c16 = idx & 7;
            uint32_t sw = swz((uint32_t)(row * ROW_BYTES + c16 * 16));
            cp_async16(stage_base + sw,
                       g_xh + (size_t)(bm + row) * K_TOT + k0 + c16 * 8);
        } else {
            int j = idx - 1024;
            int row = j >> 3, c16 = j & 7;
            uint32_t sw = swz((uint32_t)(row * ROW_BYTES + c16 * 16));
            cp_async16(stage_base + A_BYTES + sw,
                       g_wh + (size_t)(bn + row) * K_TOT + k0 + c16 * 8);
        }
    }
}

// ---------------------------------------------------------------------------
// GEMM: 128x256 block tile, BK=64, 3-stage cp.async, 16 warps x (32x64) tiles
// Register-disciplined: peak live frags = a(8) + b-half(8); acc = 64.
// ---------------------------------------------------------------------------
__global__ __launch_bounds__(NTHREADS, 1)
void qgemm_mma_kernel(const float* __restrict__ scale,
                      const float* __restrict__ bias,
                      float* __restrict__ out) {
    extern __shared__ __align__(1024) char smem[];
    const uint32_t sbase = smem_u32(smem);
    const int tid = threadIdx.x;
    const int wid = tid >> 5;
    const int l = tid & 31;

    const int bm = blockIdx.y * BM;
    const int bn = blockIdx.x * BN;
    const int wm = (wid & 3) * 32;     // warp M offset (0,32,64,96)
    const int wn = (wid >> 2) * 64;    // warp N offset (0,64,128,192)

    // scale/bias for this N tile into smem
    if (tid < BN) {
        reinterpret_cast<float*>(smem + OFF_SCALE)[tid] = scale[bn + tid];
        reinterpret_cast<float*>(smem + OFF_BIAS)[tid]  = bias[bn + tid];
    }

    float acc[2][8][4];
#pragma unroll
    for (int mi = 0; mi < 2; mi++)
#pragma unroll
        for (int ni = 0; ni < 8; ni++)
#pragma unroll
            for (int r = 0; r < 4; r++) acc[mi][ni][r] = 0.0f;

    // prologue: stages 0,1
    load_stage(tid, sbase + OFF_TILES + 0 * STAGE_BYTES, bm, bn, 0);
    CP_COMMIT();
    load_stage(tid, sbase + OFF_TILES + 1 * STAGE_BYTES, bm, bn, BK);
    CP_COMMIT();

    // per-lane ldmatrix address components (swizzle XOR constant per lane:
    // row&7 == l&7 since all added row offsets are multiples of 8)
    const uint32_t lxor = (uint32_t)((l & 7) << 4);
    const uint32_t a_row_off = (uint32_t)((wm + (l & 15)) * ROW_BYTES);
    const uint32_t a_khalf   = (uint32_t)((l >> 4) * 16);
    const uint32_t b_row_off = (uint32_t)((wn + (l & 7)) * ROW_BYTES);
    const int quad = l >> 3;
    const uint32_t b_nt_off  = (uint32_t)(((quad >> 1) * 8) * ROW_BYTES);
    const uint32_t b_khalf   = (uint32_t)((quad & 1) * 16);

    for (int it = 0; it < KITERS; it++) {
        CP_WAIT1();
        __syncthreads();

        // issue next stage's loads first (overlap with compute)
        const int nxt = it + 2;
        if (nxt < KITERS)
            load_stage(tid, sbase + OFF_TILES + (nxt % 3) * STAGE_BYTES, bm, bn, nxt * BK);
        CP_COMMIT();

        const uint32_t stA = sbase + OFF_TILES + (it % 3) * STAGE_BYTES;
        const uint32_t stB = stA + A_BYTES;

#pragma unroll
        for (int kk = 0; kk < 4; kk++) {            // k16 steps within BK=64
            // A fragments: 2 m16 tiles (warp tile M=32)
            uint32_t a[2][4];
#pragma unroll
            for (int mi = 0; mi < 2; mi++) {
                uint32_t addr = stA + a_row_off + (uint32_t)(mi * 16 * ROW_BYTES)
                              + (((uint32_t)(kk * 32) + a_khalf) ^ lxor);
                ldsm_x4(a[mi][0], a[mi][1], a[mi][2], a[mi][3], addr);
            }
            // B in two halves of 32 N each to bound register liveness
#pragma unroll
            for (int half = 0; half < 2; half++) {
                uint32_t b[4][2];
#pragma unroll
                for (int p = 0; p < 2; p++) {       // each ldsm covers 2 n8 tiles
                    const int nj = half * 2 + p;
                    uint32_t addr = stB + b_row_off + (uint32_t)(nj * 16 * ROW_BYTES)
                                  + b_nt_off
                                  + (((uint32_t)(kk * 32) + b_khalf) ^ lxor);
                    ldsm_x4(b[p * 2][0], b[p * 2][1], b[p * 2 + 1][0], b[p * 2 + 1][1], addr);
                }
#pragma unroll
                for (int mi = 0; mi < 2; mi++)
#pragma unroll
                    for (int t = 0; t < 4; t++) {
                        const int ni = half * 4 + t;
                        mma16816(acc[mi][ni][0], acc[mi][ni][1],
                                 acc[mi][ni][2], acc[mi][ni][3],
                                 a[mi][0], a[mi][1], a[mi][2], a[mi][3],
                                 b[t][0], b[t][1]);
                    }
            }
        }
    }

    // epilogue: scale/bias from smem, direct 8B stores
    const float* s_scale = reinterpret_cast<const float*>(smem + OFF_SCALE);
    const float* s_bias  = reinterpret_cast<const float*>(smem + OFF_BIAS);
    const int row0 = bm + wm + (l >> 2);
    const int col0 = wn + (l & 3) * 2;

#pragma unroll
    for (int mi = 0; mi < 2; mi++) {
#pragma unroll
        for (int ni = 0; ni < 8; ni++) {
            const int n = col0 + ni * 8;
            const float s0 = s_scale[n], s1 = s_scale[n + 1];
            const float b0 = s_bias[n],  b1 = s_bias[n + 1];
            float* p0 = out + (size_t)(row0 + mi * 16) * N_TOT + bn + n;
            float* p1 = p0 + 8 * N_TOT;
            float2 v0 = make_float2(fmaf(acc[mi][ni][0], s0, b0),
                                    fmaf(acc[mi][ni][1], s1, b1));
            float2 v1 = make_float2(fmaf(acc[mi][ni][2], s0, b0),
                                    fmaf(acc[mi][ni][3], s1, b1));
            *reinterpret_cast<float2*>(p0) = v0;
            *reinterpret_cast<float2*>(p1) = v1;
        }
    }
}

// ---------------------------------------------------------------------------
// launch
// ---------------------------------------------------------------------------
extern "C" void kernel_launch(void* const* d_in, const int* in_sizes, int n_in,
                              void* d_out, int out_size) {
    const float* x     = (const float*)d_in[0];
    const int*   w_q   = (const int*)d_in[1];
    const float* scale = (const float*)d_in[2];
    const float* bias  = (const float*)d_in[3];
    float* out = (float*)d_out;

    {
        int n4 = (M_TOT * K_TOT) / 4;
        convert_x_kernel<<<(n4 + 255) / 256, 256>>>(x, n4);
    }
    {
        int n4 = (N_TOT * K_TOT) / 4;
        convert_w_kernel<<<(n4 + 255) / 256, 256>>>(w_q, n4);
    }
    {
        static bool attr_set = false;
        if (!attr_set) {
            cudaFuncSetAttribute(qgemm_mma_kernel,
                                 cudaFuncAttributeMaxDynamicSharedMemorySize, SMEM_TOTAL);
            attr_set = true;
        }
        dim3 grid(N_TOT / BN, M_TOT / BM);  // (16, 64): x-fast shares A tiles in L2
        qgemm_mma_kernel<<<grid, NTHREADS, SMEM_TOTAL>>>(scale, bias, out);
    }
}

// round 6
// speedup vs baseline: 1.6930x; 1.0591x over previous
#include <cuda_runtime.h>
#include <cuda_fp16.h>
#include <cstdint>

static constexpr int M_TOT = 8192;   // B * S
static constexpr int N_TOT = 4096;   // D_OUT
static constexpr int K_TOT = 4096;   // D_IN

static constexpr int BM = 128;
static constexpr int BN = 256;
static constexpr int BK = 128;                     // two 64-col sub-blocks
static constexpr int SUBK = 64;
static constexpr int STAGES = 2;
static constexpr int KITERS = K_TOT / BK;          // 32
static constexpr int ROW_BYTES = SUBK * 2;         // 128 B rows (SW128 atom)
static constexpr int A_SUB = BM * ROW_BYTES;       // 16384
static constexpr int A_BYTES = 2 * A_SUB;          // 32768
static constexpr int B_SUB = BN * ROW_BYTES;       // 32768
static constexpr int B_BYTES = 2 * B_SUB;          // 65536
static constexpr int STAGE_BYTES = A_BYTES + B_BYTES;  // 98304

static constexpr int NTHREADS = 256;               // 8 warps, 64x64 warp tiles

static constexpr int OFF_SCALE = 0;                // 256 f32
static constexpr int OFF_BIAS  = 1024;             // 256 f32
static constexpr int OFF_TILES = 2048;
static constexpr int SMEM_TOTAL = OFF_TILES + STAGES * STAGE_BYTES;  // 198656

// Scratch fp16 operands (allocation-free rule: __device__ globals)
__device__ __align__(16) __half g_xh[(size_t)M_TOT * K_TOT];   // 64 MiB
__device__ __align__(16) __half g_wh[(size_t)N_TOT * K_TOT];   // 32 MiB

// ---------------------------------------------------------------------------
// helpers
// ---------------------------------------------------------------------------
__device__ __forceinline__ uint32_t smem_u32(const void* p) {
    uint32_t a;
    asm("{ .reg .u64 t; cvta.to.shared.u64 t, %1; cvt.u32.u64 %0, t; }" : "=r"(a) : "l"(p));
    return a;
}
__device__ __forceinline__ uint32_t swz(uint32_t byte_off) {
    return byte_off ^ ((byte_off >> 3) & 0x70);
}
__device__ __forceinline__ void cp_async16(uint32_t saddr, const void* gptr) {
    asm volatile("cp.async.cg.shared.global [%0], [%1], 16;" :: "r"(saddr), "l"(gptr));
}
#define CP_COMMIT() asm volatile("cp.async.commit_group;" ::: "memory")
#define CP_WAIT0()  asm volatile("cp.async.wait_group 0;" ::: "memory")

__device__ __forceinline__ void ldsm_x4(uint32_t& r0, uint32_t& r1,
                                        uint32_t& r2, uint32_t& r3, uint32_t addr) {
    asm volatile("ldmatrix.sync.aligned.m8n8.x4.shared.b16 {%0,%1,%2,%3}, [%4];"
                 : "=r"(r0), "=r"(r1), "=r"(r2), "=r"(r3) : "r"(addr));
}
__device__ __forceinline__ void mma16816(float& c0, float& c1, float& c2, float& c3,
                                         uint32_t a0, uint32_t a1, uint32_t a2, uint32_t a3,
                                         uint32_t b0, uint32_t b1) {
    asm volatile(
        "mma.sync.aligned.m16n8k16.row.col.f32.f16.f16.f32 "
        "{%0,%1,%2,%3}, {%4,%5,%6,%7}, {%8,%9}, {%0,%1,%2,%3};"
        : "+f"(c0), "+f"(c1), "+f"(c2), "+f"(c3)
        : "r"(a0), "r"(a1), "r"(a2), "r"(a3), "r"(b0), "r"(b1));
}

// ---------------------------------------------------------------------------
// conversion kernels (DRAM-streaming bound, ~68% of HBM spec)
// ---------------------------------------------------------------------------
__global__ void convert_x_kernel(const float* __restrict__ x, int n4) {
    int i = blockIdx.x * blockDim.x + threadIdx.x;
    if (i >= n4) return;
    float4 v = reinterpret_cast<const float4*>(x)[i];
    __half2* dst = reinterpret_cast<__half2*>(g_xh);
    dst[2 * i]     = __floats2half2_rn(v.x, v.y);
    dst[2 * i + 1] = __floats2half2_rn(v.z, v.w);
}
__global__ void convert_w_kernel(const int* __restrict__ w, int n4) {
    int i = blockIdx.x * blockDim.x + threadIdx.x;
    if (i >= n4) return;
    int4 v = reinterpret_cast<const int4*>(w)[i];
    __half2* dst = reinterpret_cast<__half2*>(g_wh);
    dst[2 * i]     = __halves2half2(__int2half_rn(v.x), __int2half_rn(v.y));
    dst[2 * i + 1] = __halves2half2(__int2half_rn(v.z), __int2half_rn(v.w));
}

// ---------------------------------------------------------------------------
// stage loader: 6144 x 16B cp.async (A: 2048, B: 4096 chunks), SW128 per sub
// ---------------------------------------------------------------------------
__device__ __forceinline__ void load_stage(int tid, uint32_t stage_base,
                                           int bm, int bn, int k0) {
#pragma unroll
    for (int i = 0; i < 24; i++) {
        int idx = tid + i * NTHREADS;
        if (idx < 2048) {                     // A: row(7b) | sub(1b) | c16(3b)
            int r   = idx >> 4;
            int s   = (idx >> 3) & 1;
            int c16 = idx & 7;
            uint32_t sw = swz((uint32_t)(r * ROW_BYTES + c16 * 16));
            cp_async16(stage_base + s * A_SUB + sw,
                       g_xh + (size_t)(bm + r) * K_TOT + k0 + s * SUBK + c16 * 8);
        } else {                              // B
            int j   = idx - 2048;
            int r   = j >> 4;
            int s   = (j >> 3) & 1;
            int c16 = j & 7;
            uint32_t sw = swz((uint32_t)(r * ROW_BYTES + c16 * 16));
            cp_async16(stage_base + A_BYTES + s * B_SUB + sw,
                       g_wh + (size_t)(bn + r) * K_TOT + k0 + s * SUBK + c16 * 8);
        }
    }
}

// ---------------------------------------------------------------------------
// GEMM: 128x256 block tile, BK=128 (2 sub-blocks), 2-stage cp.async,
//       8 warps x (64x64) warp tiles
// ---------------------------------------------------------------------------
__global__ __launch_bounds__(NTHREADS, 1)
void qgemm_mma_kernel(const float* __restrict__ scale,
                      const float* __restrict__ bias,
                      float* __restrict__ out) {
    extern __shared__ __align__(1024) char smem[];
    const uint32_t sbase = smem_u32(smem);
    const int tid = threadIdx.x;
    const int wid = tid >> 5;
    const int l = tid & 31;

    const int bm = blockIdx.y * BM;
    const int bn = blockIdx.x * BN;
    const int wm = (wid & 1) * 64;     // warp M offset (0 or 64)
    const int wn = (wid >> 1) * 64;    // warp N offset (0,64,128,192)

    // scale/bias for this N tile into smem (256 threads == BN)
    reinterpret_cast<float*>(smem + OFF_SCALE)[tid] = scale[bn + tid];
    reinterpret_cast<float*>(smem + OFF_BIAS)[tid]  = bias[bn + tid];

    float acc[4][8][4];
#pragma unroll
    for (int mi = 0; mi < 4; mi++)
#pragma unroll
        for (int ni = 0; ni < 8; ni++)
#pragma unroll
            for (int r = 0; r < 4; r++) acc[mi][ni][r] = 0.0f;

    // prologue: stage 0
    load_stage(tid, sbase + OFF_TILES, bm, bn, 0);
    CP_COMMIT();

    // per-lane ldmatrix address components (swizzle XOR constant per lane:
    // row&7 == l&7 since all added row offsets are multiples of 8)
    const uint32_t lxor = (uint32_t)((l & 7) << 4);
    const uint32_t a_row_off = (uint32_t)((wm + (l & 15)) * ROW_BYTES);
    const uint32_t a_khalf   = (uint32_t)((l >> 4) * 16);
    const uint32_t b_row_off = (uint32_t)((wn + (l & 7)) * ROW_BYTES);
    const int quad = l >> 3;
    const uint32_t b_nt_off  = (uint32_t)(((quad >> 1) * 8) * ROW_BYTES);
    const uint32_t b_khalf   = (uint32_t)((quad & 1) * 16);

    for (int it = 0; it < KITERS; it++) {
        CP_WAIT0();            // stage `it` resident
        __syncthreads();       // all warps done with the other buffer

        // prefetch stage it+1 into the other buffer (overlaps compute below)
        if (it + 1 < KITERS)
            load_stage(tid, sbase + OFF_TILES + ((it + 1) & 1) * STAGE_BYTES,
                       bm, bn, (it + 1) * BK);
        CP_COMMIT();

        const uint32_t st = sbase + OFF_TILES + (it & 1) * STAGE_BYTES;

#pragma unroll
        for (int sub = 0; sub < 2; sub++) {
            const uint32_t stA = st + sub * A_SUB;
            const uint32_t stB = st + A_BYTES + sub * B_SUB;
#pragma unroll
            for (int kk = 0; kk < 4; kk++) {        // k16 steps within SUBK=64
                uint32_t a[4][4], b[8][2];
#pragma unroll
                for (int mi = 0; mi < 4; mi++) {
                    uint32_t addr = stA + a_row_off + (uint32_t)(mi * 16 * ROW_BYTES)
                                  + (((uint32_t)(kk * 32) + a_khalf) ^ lxor);
                    ldsm_x4(a[mi][0], a[mi][1], a[mi][2], a[mi][3], addr);
                }
#pragma unroll
                for (int nj = 0; nj < 4; nj++) {    // each x4 covers 2 n8 tiles
                    uint32_t addr = stB + b_row_off + (uint32_t)(nj * 16 * ROW_BYTES)
                                  + b_nt_off
                                  + (((uint32_t)(kk * 32) + b_khalf) ^ lxor);
                    ldsm_x4(b[nj * 2][0], b[nj * 2][1],
                            b[nj * 2 + 1][0], b[nj * 2 + 1][1], addr);
                }
#pragma unroll
                for (int mi = 0; mi < 4; mi++)
#pragma unroll
                    for (int ni = 0; ni < 8; ni++)
                        mma16816(acc[mi][ni][0], acc[mi][ni][1],
                                 acc[mi][ni][2], acc[mi][ni][3],
                                 a[mi][0], a[mi][1], a[mi][2], a[mi][3],
                                 b[ni][0], b[ni][1]);
            }
        }
    }

    // epilogue: scale/bias from smem, direct 8B stores
    const float* s_scale = reinterpret_cast<const float*>(smem + OFF_SCALE);
    const float* s_bias  = reinterpret_cast<const float*>(smem + OFF_BIAS);
    const int row0 = bm + wm + (l >> 2);
    const int col0 = wn + (l & 3) * 2;

#pragma unroll
    for (int mi = 0; mi < 4; mi++) {
#pragma unroll
        for (int ni = 0; ni < 8; ni++) {
            const int n = col0 + ni * 8;
            const float s0 = s_scale[n], s1 = s_scale[n + 1];
            const float b0 = s_bias[n],  b1 = s_bias[n + 1];
            float* p0 = out + (size_t)(row0 + mi * 16) * N_TOT + bn + n;
            float* p1 = p0 + 8 * N_TOT;
            float2 v0 = make_float2(fmaf(acc[mi][ni][0], s0, b0),
                                    fmaf(acc[mi][ni][1], s1, b1));
            float2 v1 = make_float2(fmaf(acc[mi][ni][2], s0, b0),
                                    fmaf(acc[mi][ni][3], s1, b1));
            *reinterpret_cast<float2*>(p0) = v0;
            *reinterpret_cast<float2*>(p1) = v1;
        }
    }
}

// ---------------------------------------------------------------------------
// launch
// ---------------------------------------------------------------------------
extern "C" void kernel_launch(void* const* d_in, const int* in_sizes, int n_in,
                              void* d_out, int out_size) {
    const float* x     = (const float*)d_in[0];
    const int*   w_q   = (const int*)d_in[1];
    const float* scale = (const float*)d_in[2];
    const float* bias  = (const float*)d_in[3];
    float* out = (float*)d_out;

    {
        int n4 = (M_TOT * K_TOT) / 4;
        convert_x_kernel<<<(n4 + 255) / 256, 256>>>(x, n4);
    }
    {
        int n4 = (N_TOT * K_TOT) / 4;
        convert_w_kernel<<<(n4 + 255) / 256, 256>>>(w_q, n4);
    }
    {
        static bool attr_set = false;
        if (!attr_set) {
            cudaFuncSetAttribute(qgemm_mma_kernel,
                                 cudaFuncAttributeMaxDynamicSharedMemorySize, SMEM_TOTAL);
            attr_set = true;
        }
        dim3 grid(N_TOT / BN, M_TOT / BM);  // (16, 64): x-fast shares A tiles in L2
        qgemm_mma_kernel<<<grid, NTHREADS, SMEM_TOTAL>>>(scale, bias, out);
    }
}

// round 7
// speedup vs baseline: 1.6979x; 1.0029x over previous
#include <cuda_runtime.h>
#include <cuda_fp16.h>
#include <cstdint>

static constexpr int M_TOT = 8192;   // B * S
static constexpr int N_TOT = 4096;   // D_OUT
static constexpr int K_TOT = 4096;   // D_IN

static constexpr int BM = 128;
static constexpr int BN = 256;
static constexpr int BK = 128;                     // two 64-col sub-blocks
static constexpr int SUBK = 64;
static constexpr int STAGES = 2;
static constexpr int KITERS = K_TOT / BK;          // 32
static constexpr int ROW_BYTES = SUBK * 2;         // 128 B rows (SW128 atom)
static constexpr int A_SUB = BM * ROW_BYTES;       // 16384
static constexpr int A_BYTES = 2 * A_SUB;          // 32768
static constexpr int B_SUB = BN * ROW_BYTES;       // 32768
static constexpr int B_BYTES = 2 * B_SUB;          // 65536
static constexpr int STAGE_BYTES = A_BYTES + B_BYTES;  // 98304

static constexpr int NTHREADS = 256;               // 8 warps, 64x64 warp tiles

static constexpr int OFF_SCALE = 0;                // 256 f32
static constexpr int OFF_BIAS  = 1024;             // 256 f32
static constexpr int OFF_TILES = 2048;
static constexpr int SMEM_TOTAL = OFF_TILES + STAGES * STAGE_BYTES;  // 198656

// Scratch fp16 operands (allocation-free rule: __device__ globals)
__device__ __align__(16) __half g_xh[(size_t)M_TOT * K_TOT];   // 64 MiB
__device__ __align__(16) __half g_wh[(size_t)N_TOT * K_TOT];   // 32 MiB

// ---------------------------------------------------------------------------
// helpers
// ---------------------------------------------------------------------------
__device__ __forceinline__ uint32_t smem_u32(const void* p) {
    uint32_t a;
    asm("{ .reg .u64 t; cvta.to.shared.u64 t, %1; cvt.u32.u64 %0, t; }" : "=r"(a) : "l"(p));
    return a;
}
__device__ __forceinline__ uint32_t swz(uint32_t byte_off) {
    return byte_off ^ ((byte_off >> 3) & 0x70);
}
__device__ __forceinline__ void cp_async16(uint32_t saddr, const void* gptr) {
    asm volatile("cp.async.cg.shared.global [%0], [%1], 16;" :: "r"(saddr), "l"(gptr));
}
#define CP_COMMIT() asm volatile("cp.async.commit_group;" ::: "memory")
#define CP_WAIT0()  asm volatile("cp.async.wait_group 0;" ::: "memory")

__device__ __forceinline__ void ldsm_x4(uint32_t& r0, uint32_t& r1,
                                        uint32_t& r2, uint32_t& r3, uint32_t addr) {
    asm volatile("ldmatrix.sync.aligned.m8n8.x4.shared.b16 {%0,%1,%2,%3}, [%4];"
                 : "=r"(r0), "=r"(r1), "=r"(r2), "=r"(r3) : "r"(addr));
}
__device__ __forceinline__ void mma16816(float& c0, float& c1, float& c2, float& c3,
                                         uint32_t a0, uint32_t a1, uint32_t a2, uint32_t a3,
                                         uint32_t b0, uint32_t b1) {
    asm volatile(
        "mma.sync.aligned.m16n8k16.row.col.f32.f16.f16.f32 "
        "{%0,%1,%2,%3}, {%4,%5,%6,%7}, {%8,%9}, {%0,%1,%2,%3};"
        : "+f"(c0), "+f"(c1), "+f"(c2), "+f"(c3)
        : "r"(a0), "r"(a1), "r"(a2), "r"(a3), "r"(b0), "r"(b1));
}

// ---------------------------------------------------------------------------
// fused conversion kernel: fp32->fp16 (x) and int32->fp16 (w) in one launch
// (keeps total launches/call at 2 so ncu -s 5 lands on the GEMM)
// ---------------------------------------------------------------------------
static constexpr int N4X = (M_TOT * K_TOT) / 4;    // 8388608
static constexpr int N4W = (N_TOT * K_TOT) / 4;    // 4194304

__global__ void convert_all_kernel(const float* __restrict__ x,
                                   const int* __restrict__ w) {
    int i = blockIdx.x * blockDim.x + threadIdx.x;
    if (i < N4X) {
        float4 v = reinterpret_cast<const float4*>(x)[i];
        __half2* dst = reinterpret_cast<__half2*>(g_xh);
        dst[2 * i]     = __floats2half2_rn(v.x, v.y);
        dst[2 * i + 1] = __floats2half2_rn(v.z, v.w);
    } else {
        int j = i - N4X;
        if (j < N4W) {
            int4 v = reinterpret_cast<const int4*>(w)[j];
            __half2* dst = reinterpret_cast<__half2*>(g_wh);
            dst[2 * j]     = __halves2half2(__int2half_rn(v.x), __int2half_rn(v.y));
            dst[2 * j + 1] = __halves2half2(__int2half_rn(v.z), __int2half_rn(v.w));
        }
    }
}

// ---------------------------------------------------------------------------
// stage loader: 6144 x 16B cp.async (A: 2048, B: 4096 chunks), SW128 per sub
// ---------------------------------------------------------------------------
__device__ __forceinline__ void load_stage(int tid, uint32_t stage_base,
                                           int bm, int bn, int k0) {
#pragma unroll
    for (int i = 0; i < 24; i++) {
        int idx = tid + i * NTHREADS;
        if (idx < 2048) {                     // A: row(7b) | sub(1b) | c16(3b)
            int r   = idx >> 4;
            int s   = (idx >> 3) & 1;
            int c16 = idx & 7;
            uint32_t sw = swz((uint32_t)(r * ROW_BYTES + c16 * 16));
            cp_async16(stage_base + s * A_SUB + sw,
                       g_xh + (size_t)(bm + r) * K_TOT + k0 + s * SUBK + c16 * 8);
        } else {                              // B
            int j   = idx - 2048;
            int r   = j >> 4;
            int s   = (j >> 3) & 1;
            int c16 = j & 7;
            uint32_t sw = swz((uint32_t)(r * ROW_BYTES + c16 * 16));
            cp_async16(stage_base + A_BYTES + s * B_SUB + sw,
                       g_wh + (size_t)(bn + r) * K_TOT + k0 + s * SUBK + c16 * 8);
        }
    }
}

// ---------------------------------------------------------------------------
// GEMM: 128x256 block tile, BK=128, 2-stage cp.async, 8 warps x (64x64),
//       fragment double-buffering across the 8 k16 steps per iteration
// ---------------------------------------------------------------------------
__global__ __launch_bounds__(NTHREADS, 1)
void qgemm_mma_kernel(const float* __restrict__ scale,
                      const float* __restrict__ bias,
                      float* __restrict__ out) {
    extern __shared__ __align__(1024) char smem[];
    const uint32_t sbase = smem_u32(smem);
    const int tid = threadIdx.x;
    const int wid = tid >> 5;
    const int l = tid & 31;

    const int bm = blockIdx.y * BM;
    const int bn = blockIdx.x * BN;
    const int wm = (wid & 1) * 64;     // warp M offset (0 or 64)
    const int wn = (wid >> 1) * 64;    // warp N offset (0,64,128,192)

    // scale/bias for this N tile into smem (256 threads == BN)
    reinterpret_cast<float*>(smem + OFF_SCALE)[tid] = scale[bn + tid];
    reinterpret_cast<float*>(smem + OFF_BIAS)[tid]  = bias[bn + tid];

    float acc[4][8][4];
#pragma unroll
    for (int mi = 0; mi < 4; mi++)
#pragma unroll
        for (int ni = 0; ni < 8; ni++)
#pragma unroll
            for (int r = 0; r < 4; r++) acc[mi][ni][r] = 0.0f;

    // prologue: stage 0
    load_stage(tid, sbase + OFF_TILES, bm, bn, 0);
    CP_COMMIT();

    // per-lane ldmatrix address components (swizzle XOR constant per lane:
    // row&7 == l&7 since all added row offsets are multiples of 8)
    const uint32_t lxor = (uint32_t)((l & 7) << 4);
    const uint32_t a_row_off = (uint32_t)((wm + (l & 15)) * ROW_BYTES);
    const uint32_t a_khalf   = (uint32_t)((l >> 4) * 16);
    const uint32_t b_row_off = (uint32_t)((wn + (l & 7)) * ROW_BYTES);
    const int quad = l >> 3;
    const uint32_t b_nt_off  = (uint32_t)(((quad >> 1) * 8) * ROW_BYTES);
    const uint32_t b_khalf   = (uint32_t)((quad & 1) * 16);

    // fragment double buffers
    uint32_t a[2][4][4], b[2][8][2];

    // step s (0..7): sub = s>>2, kk = s&3
#define LOAD_FRAGS(buf, st, s)                                                  \
    do {                                                                        \
        const uint32_t _stA = (st) + ((s) >> 2) * A_SUB;                        \
        const uint32_t _stB = (st) + A_BYTES + ((s) >> 2) * B_SUB;              \
        const uint32_t _koff = (uint32_t)(((s) & 3) * 32);                      \
        _Pragma("unroll")                                                       \
        for (int mi = 0; mi < 4; mi++) {                                        \
            uint32_t addr = _stA + a_row_off + (uint32_t)(mi * 16 * ROW_BYTES)  \
                          + ((_koff + a_khalf) ^ lxor);                         \
            ldsm_x4(a[buf][mi][0], a[buf][mi][1], a[buf][mi][2], a[buf][mi][3], \
                    addr);                                                      \
        }                                                                       \
        _Pragma("unroll")                                                       \
        for (int nj = 0; nj < 4; nj++) {                                        \
            uint32_t addr = _stB + b_row_off + (uint32_t)(nj * 16 * ROW_BYTES)  \
                          + b_nt_off + ((_koff + b_khalf) ^ lxor);              \
            ldsm_x4(b[buf][nj * 2][0], b[buf][nj * 2][1],                       \
                    b[buf][nj * 2 + 1][0], b[buf][nj * 2 + 1][1], addr);        \
        }                                                                       \
    } while (0)

#define MMA_STEP(buf)                                                           \
    do {                                                                        \
        _Pragma("unroll")                                                       \
        for (int mi = 0; mi < 4; mi++)                                          \
            _Pragma("unroll")                                                   \
            for (int ni = 0; ni < 8; ni++)                                      \
                mma16816(acc[mi][ni][0], acc[mi][ni][1],                        \
                         acc[mi][ni][2], acc[mi][ni][3],                        \
                         a[buf][mi][0], a[buf][mi][1],                          \
                         a[buf][mi][2], a[buf][mi][3],                          \
                         b[buf][ni][0], b[buf][ni][1]);                         \
    } while (0)

    for (int it = 0; it < KITERS; it++) {
        CP_WAIT0();            // stage `it` resident
        __syncthreads();       // all warps done with the other buffer

        // prefetch stage it+1 into the other buffer (overlaps compute below)
        if (it + 1 < KITERS)
            load_stage(tid, sbase + OFF_TILES + ((it + 1) & 1) * STAGE_BYTES,
                       bm, bn, (it + 1) * BK);
        CP_COMMIT();

        const uint32_t st = sbase + OFF_TILES + (it & 1) * STAGE_BYTES;

        // software-pipelined 8 k16 steps: load s+1 while computing s
        LOAD_FRAGS(0, st, 0);
#pragma unroll
        for (int s = 0; s < 7; s++) {
            LOAD_FRAGS((s + 1) & 1, st, s + 1);
            MMA_STEP(s & 1);
        }
        MMA_STEP(1);           // step 7 lives in buffer 1
    }

    // epilogue: scale/bias from smem, direct 8B stores
    const float* s_scale = reinterpret_cast<const float*>(smem + OFF_SCALE);
    const float* s_bias  = reinterpret_cast<const float*>(smem + OFF_BIAS);
    const int row0 = bm + wm + (l >> 2);
    const int col0 = wn + (l & 3) * 2;

#pragma unroll
    for (int mi = 0; mi < 4; mi++) {
#pragma unroll
        for (int ni = 0; ni < 8; ni++) {
            const int n = col0 + ni * 8;
            const float s0 = s_scale[n], s1 = s_scale[n + 1];
            const float b0 = s_bias[n],  b1 = s_bias[n + 1];
            float* p0 = out + (size_t)(row0 + mi * 16) * N_TOT + bn + n;
            float* p1 = p0 + 8 * N_TOT;
            float2 v0 = make_float2(fmaf(acc[mi][ni][0], s0, b0),
                                    fmaf(acc[mi][ni][1], s1, b1));
            float2 v1 = make_float2(fmaf(acc[mi][ni][2], s0, b0),
                                    fmaf(acc[mi][ni][3], s1, b1));
            *reinterpret_cast<float2*>(p0) = v0;
            *reinterpret_cast<float2*>(p1) = v1;
        }
    }
}

// ---------------------------------------------------------------------------
// launch
// ---------------------------------------------------------------------------
extern "C" void kernel_launch(void* const* d_in, const int* in_sizes, int n_in,
                              void* d_out, int out_size) {
    const float* x     = (const float*)d_in[0];
    const int*   w_q   = (const int*)d_in[1];
    const float* scale = (const float*)d_in[2];
    const float* bias  = (const float*)d_in[3];
    float* out = (float*)d_out;

    {
        int total = N4X + N4W;
        convert_all_kernel<<<(total + 255) / 256, 256>>>(x, w_q);
    }
    {
        static bool attr_set = false;
        if (!attr_set) {
            cudaFuncSetAttribute(qgemm_mma_kernel,
                                 cudaFuncAttributeMaxDynamicSharedMemorySize, SMEM_TOTAL);
            attr_set = true;
        }
        dim3 grid(N_TOT / BN, M_TOT / BM);  // (16, 64): x-fast shares A tiles in L2
        qgemm_mma_kernel<<<grid, NTHREADS, SMEM_TOTAL>>>(scale, bias, out);
    }
}